// round 2
// baseline (speedup 1.0000x reference)
#include <cuda_runtime.h>
#include <cstdint>

// Problem constants
#define NLV 8
#define NEI 8
#define NB  524288          // BATCH = 2^19
#define NB_SHIFT 19
#define NPIX 196608
#define TOT (NLV * NEI * NB)    // 33,554,432 entries

#define SZ_PARAMS 3145728       // 8*196608*2
#define SZ_PIXEL  8388608       // 8*524288*2
#define SZ_NEIGH  67108864      // 8*8*524288*2
#define SZ_IDXMSK 33554432      // 8*8*524288

#define P1_THREADS 256
#define P1_BLOCKS  ((NLV * NB) / P1_THREADS)   // 16384
#define P2_THREADS 256
#define P2_BLOCKS  (NB / P2_THREADS)           // 2048

// Scratch: masked distances (mask==0 -> 1e30 sentinel), 134 MB static device mem
__device__ float g_scratch[TOT];
__device__ float g_blockmax[P1_BLOCKS];
__device__ float g_max;

// Probe results: g_swap: candA is the MASK (and candB the index). g_mask_i32: mask stored as int32.
__device__ int g_swap;
__device__ int g_mask_i32;

__device__ __forceinline__ float sqrt_approx(float x) {
    float r; asm("sqrt.approx.f32 %0, %1;" : "=f"(r) : "f"(x)); return r;
}
__device__ __forceinline__ float rcp_approx(float x) {
    float r; asm("rcp.approx.f32 %0, %1;" : "=f"(r) : "f"(x)); return r;
}

// atan(t) for t in [0,1], degree-11 odd minimax, |err| ~ 1e-6
__device__ __forceinline__ float atan_poly(float t) {
    float t2 = t * t;
    float p = -0.0117212f;
    p = fmaf(p, t2, 0.05265332f);
    p = fmaf(p, t2, -0.11643287f);
    p = fmaf(p, t2, 0.19354346f);
    p = fmaf(p, t2, -0.33262347f);
    p = fmaf(p, t2, 0.99997726f);
    return t * p;
}

// dist = 2 * atan2(sqrt(clip(a,0)), sqrt(clip(1-a,0)))  ==  2*asin(sqrt(clip01(a)))
__device__ __forceinline__ float dist_from_a(float a) {
    float ac   = fminf(fmaxf(a, 0.0f), 1.0f);
    float amin = fminf(ac, 1.0f - ac);
    float amax = 1.0f - amin;                            // >= 0.5, rcp safe
    float t    = sqrt_approx(amin * rcp_approx(amax));   // in [0,1]
    float at   = atan_poly(t);
    float half = (ac <= 0.5f) ? at : (1.5707963267948966f - at);
    return 2.0f * half;
}

// ---------------------------------------------------------------------------
// Probe: classify the two 33.5M-element arrays (index vs mask, mask dtype).
// Samples 4096 int32s strided across the first 8M int32s (= min footprint,
// safe even if the array is 1-byte bool). Classification per array:
//   all values in {0,1}        -> int32 mask
//   all values in [0, NPIX)    -> index
//   otherwise (packed bytes)   -> uint8 mask
// ---------------------------------------------------------------------------
__global__ void probe_kernel(const int* __restrict__ A, const int* __restrict__ B)
{
    __shared__ int fA_not01, fA_oor, fB_not01, fB_oor;
    if (threadIdx.x == 0) { fA_not01 = 0; fA_oor = 0; fB_not01 = 0; fB_oor = 0; }
    __syncthreads();

    int a_not01 = 0, a_oor = 0, b_not01 = 0, b_oor = 0;
    for (int i = threadIdx.x; i < 4096; i += 256) {
        int j = i * 2048;                 // max 8,386,560 < 8,388,608 int32s
        int va = A[j];
        int vb = B[j];
        if (va != 0 && va != 1) a_not01 = 1;
        if (va < 0 || va >= NPIX) a_oor = 1;
        if (vb != 0 && vb != 1) b_not01 = 1;
        if (vb < 0 || vb >= NPIX) b_oor = 1;
    }
    if (a_not01) atomicOr(&fA_not01, 1);
    if (a_oor)   atomicOr(&fA_oor, 1);
    if (b_not01) atomicOr(&fB_not01, 1);
    if (b_oor)   atomicOr(&fB_oor, 1);
    __syncthreads();

    if (threadIdx.x == 0) {
        int swap, mi32;
        if (!fA_not01) {                  // A is an int32 mask
            swap = 1; mi32 = 1;
        } else if (!fA_oor) {             // A is the index array
            swap = 0;
            mi32 = (!fB_not01) ? 1 : 0;   // classify B's mask dtype
        } else {                          // A has packed-byte garbage -> uint8 mask
            swap = 1; mi32 = 0;
        }
        g_swap = swap;
        g_mask_i32 = mi32;
    }
}

__global__ __launch_bounds__(P1_THREADS)
void pass1_kernel(const float2* __restrict__ pixel,      // [NLV*NB]
                  const float2* __restrict__ neigh,      // [NLV*NEI*NB]
                  const void*   __restrict__ candA,
                  const void*   __restrict__ candB)
{
    const int swap = g_swap;
    const int mi32 = g_mask_i32;
    const void* maskp = swap ? candA : candB;

    int t = blockIdx.x * P1_THREADS + threadIdx.x;   // t in [0, NLV*NB)
    int l = t >> NB_SHIFT;
    int b = t & (NB - 1);

    float2 p = pixel[t];
    float lat1 = p.x, lon1 = p.y;
    float cl1 = __cosf(lat1);

    int base = (l * NEI) * NB + b;

    // Front-batch all loads for MLP
    float2 q[NEI];
    int    m[NEI];
#pragma unroll
    for (int e = 0; e < NEI; e++)
        q[e] = neigh[base + e * NB];
    if (mi32) {
        const int* mp = (const int*)maskp;
#pragma unroll
        for (int e = 0; e < NEI; e++) m[e] = mp[base + e * NB];
    } else {
        const uint8_t* mp = (const uint8_t*)maskp;
#pragma unroll
        for (int e = 0; e < NEI; e++) m[e] = mp[base + e * NB];
    }

    float lmax = 0.0f;
#pragma unroll
    for (int e = 0; e < NEI; e++) {
        float dlat = q[e].x - lat1;
        float dlon = q[e].y - lon1;
        float s1 = __sinf(0.5f * dlat);
        float s2 = __sinf(0.5f * dlon);
        float cl2 = __cosf(q[e].x);
        float a = fmaf(s1, s1, cl1 * cl2 * (s2 * s2));
        float d = dist_from_a(a);
        lmax = fmaxf(lmax, d);                            // max over ALL entries
        g_scratch[base + e * NB] = m[e] ? d : 1e30f;      // sentinel -> weight 0
    }

    // warp + block max reduce
#pragma unroll
    for (int s = 16; s > 0; s >>= 1)
        lmax = fmaxf(lmax, __shfl_xor_sync(0xFFFFFFFFu, lmax, s));

    __shared__ float sm[P1_THREADS / 32];
    int lane = threadIdx.x & 31;
    int wid  = threadIdx.x >> 5;
    if (lane == 0) sm[wid] = lmax;
    __syncthreads();
    if (threadIdx.x == 0) {
        float bm = sm[0];
#pragma unroll
        for (int i = 1; i < P1_THREADS / 32; i++) bm = fmaxf(bm, sm[i]);
        g_blockmax[blockIdx.x] = bm;
    }
}

__global__ __launch_bounds__(1024)
void reduce_kernel()
{
    float m = 0.0f;
    for (int i = threadIdx.x; i < P1_BLOCKS; i += 1024)
        m = fmaxf(m, g_blockmax[i]);
#pragma unroll
    for (int s = 16; s > 0; s >>= 1)
        m = fmaxf(m, __shfl_xor_sync(0xFFFFFFFFu, m, s));
    __shared__ float sm[32];
    int lane = threadIdx.x & 31;
    int wid  = threadIdx.x >> 5;
    if (lane == 0) sm[wid] = m;
    __syncthreads();
    if (threadIdx.x == 0) {
        float bm = sm[0];
#pragma unroll
        for (int i = 1; i < 32; i++) bm = fmaxf(bm, sm[i]);
        g_max = bm;
    }
}

__global__ __launch_bounds__(P2_THREADS)
void pass2_kernel(const float2* __restrict__ params,     // [NLV*NPIX]
                  const void*   __restrict__ candA,
                  const void*   __restrict__ candB,
                  float*        __restrict__ out)        // [NB, 2*NLV]
{
    const int swap = g_swap;
    const int* nidx = (const int*)(swap ? candB : candA);

    int b = blockIdx.x * P2_THREADS + threadIdx.x;
    float gmax = g_max;

    float o[2 * NLV];

#pragma unroll
    for (int l = 0; l < NLV; l++) {
        int base = (l * NEI) * NB + b;
        float d[NEI];
        int   id[NEI];
#pragma unroll
        for (int e = 0; e < NEI; e++) {
            d[e]  = g_scratch[base + e * NB];
            id[e] = nidx[base + e * NB];
        }
        float ax = 0.0f, ay = 0.0f;
#pragma unroll
        for (int e = 0; e < NEI; e++) {
            float w = fmaxf(gmax - d[e], 0.0f);      // sentinel 1e30 -> exactly 0
            float2 pp = params[l * NPIX + id[e]];
            ax = fmaf(pp.x, w, ax);
            ay = fmaf(pp.y, w, ay);
        }
        o[l]       = ax;     // f=0 block: positions [0..7]
        o[NLV + l] = ay;     // f=1 block: positions [8..15]
    }

    float4* o4 = reinterpret_cast<float4*>(out + (size_t)b * (2 * NLV));
#pragma unroll
    for (int i = 0; i < (2 * NLV) / 4; i++)
        o4[i] = make_float4(o[4 * i], o[4 * i + 1], o[4 * i + 2], o[4 * i + 3]);
}

extern "C" void kernel_launch(void* const* d_in, const int* in_sizes, int n_in,
                              void* d_out, int out_size)
{
    (void)out_size;
    // Size-based dispatch: robust to any input ordering.
    const float2* params = nullptr;
    const float2* pixel  = nullptr;
    const float2* neigh  = nullptr;
    const void*   candA  = nullptr;   // first 33.5M-element array (index in both known orderings)
    const void*   candB  = nullptr;   // second 33.5M-element array
    for (int i = 0; i < n_in; i++) {
        switch (in_sizes[i]) {
            case SZ_PARAMS: params = (const float2*)d_in[i]; break;
            case SZ_PIXEL:  pixel  = (const float2*)d_in[i]; break;
            case SZ_NEIGH:  neigh  = (const float2*)d_in[i]; break;
            case SZ_IDXMSK:
                if (!candA) candA = d_in[i]; else candB = d_in[i];
                break;
            default: break;
        }
    }
    float* out = (float*)d_out;

    probe_kernel<<<1, 256>>>((const int*)candA, (const int*)candB);
    pass1_kernel<<<P1_BLOCKS, P1_THREADS>>>(pixel, neigh, candA, candB);
    reduce_kernel<<<1, 1024>>>();
    pass2_kernel<<<P2_BLOCKS, P2_THREADS>>>(params, candA, candB, out);
}

// round 5
// speedup vs baseline: 1.5782x; 1.5782x over previous
#include <cuda_runtime.h>
#include <cstdint>

// R5 resubmit of the fused kernel (R3/R4 never ran: infra container failures).

// Problem constants
#define NLV 8
#define NEI 8
#define NB  524288          // BATCH = 2^19
#define NB_SHIFT 19
#define NPIX 196608
#define NLB (NLV * NB)          // 4,194,304

#define SZ_PARAMS 3145728       // 8*196608*2
#define SZ_PIXEL  8388608       // 8*524288*2
#define SZ_NEIGH  67108864      // 8*8*524288*2
#define SZ_IDXMSK 33554432      // 8*8*524288

#define P1_THREADS 256
#define P1_BLOCKS  (NLB / P1_THREADS)          // 16384
#define P2_THREADS 256
#define P2_BLOCKS  (NB / P2_THREADS)           // 2048

// Partial sums per (l,b): (S1.x, S1.y, S2.x, S2.y) where
//   S1 = sum_e m_e * p_e,  S2 = sum_e m_e * d_e * p_e.
// out = gmax*S1 - S2. 67 MB static device scratch.
__device__ float4 g_sums[NLB];
__device__ float  g_blockmax[P1_BLOCKS];
__device__ float  g_max;

// Probe results: g_swap: candA is the MASK (candB the index). g_mask_i32: mask is int32.
__device__ int g_swap;
__device__ int g_mask_i32;

__device__ __forceinline__ float sqrt_approx(float x) {
    float r; asm("sqrt.approx.f32 %0, %1;" : "=f"(r) : "f"(x)); return r;
}
__device__ __forceinline__ float rcp_approx(float x) {
    float r; asm("rcp.approx.f32 %0, %1;" : "=f"(r) : "f"(x)); return r;
}

// atan(t) for t in [0,1], degree-11 odd minimax, |err| ~ 1e-6
__device__ __forceinline__ float atan_poly(float t) {
    float t2 = t * t;
    float p = -0.0117212f;
    p = fmaf(p, t2, 0.05265332f);
    p = fmaf(p, t2, -0.11643287f);
    p = fmaf(p, t2, 0.19354346f);
    p = fmaf(p, t2, -0.33262347f);
    p = fmaf(p, t2, 0.99997726f);
    return t * p;
}

// dist = 2*atan2(sqrt(clip(a,0)), sqrt(clip(1-a,0))) == 2*asin(sqrt(clip01(a)))
__device__ __forceinline__ float dist_from_a(float a) {
    float ac   = fminf(fmaxf(a, 0.0f), 1.0f);
    float amin = fminf(ac, 1.0f - ac);
    float amax = 1.0f - amin;                            // >= 0.5, rcp safe
    float t    = sqrt_approx(amin * rcp_approx(amax));   // in [0,1]
    float at   = atan_poly(t);
    float half = (ac <= 0.5f) ? at : (1.5707963267948966f - at);
    return 2.0f * half;
}

// ---------------------------------------------------------------------------
// Probe: classify the two 33.5M-element arrays (index vs mask, mask dtype).
// Samples strided int32s within the minimum possible footprint (33.5 MB).
// ---------------------------------------------------------------------------
__global__ void probe_kernel(const int* __restrict__ A, const int* __restrict__ B)
{
    __shared__ int fA_not01, fA_oor, fB_not01;
    if (threadIdx.x == 0) { fA_not01 = 0; fA_oor = 0; fB_not01 = 0; }
    __syncthreads();

    int a_not01 = 0, a_oor = 0, b_not01 = 0;
    for (int i = threadIdx.x; i < 4096; i += 256) {
        int j = i * 2048;                 // max 8,386,560 < 8,388,608 int32s (min footprint)
        int va = A[j];
        int vb = B[j];
        if (va != 0 && va != 1) a_not01 = 1;
        if (va < 0 || va >= NPIX) a_oor = 1;
        if (vb != 0 && vb != 1) b_not01 = 1;
    }
    if (a_not01) atomicOr(&fA_not01, 1);
    if (a_oor)   atomicOr(&fA_oor, 1);
    if (b_not01) atomicOr(&fB_not01, 1);
    __syncthreads();

    if (threadIdx.x == 0) {
        int swap, mi32;
        if (!fA_not01)      { swap = 1; mi32 = 1; }               // A is int32 mask
        else if (!fA_oor)   { swap = 0; mi32 = (!fB_not01); }     // A is index
        else                { swap = 1; mi32 = 0; }               // A is packed uint8 mask
        g_swap = swap;
        g_mask_i32 = mi32;
    }
}

// ---------------------------------------------------------------------------
// Fused pass 1: distances + global-max partials + MASKED param gather folded
// into two linear partial sums (gather overlaps the DRAM-bound streaming).
// ---------------------------------------------------------------------------
__global__ __launch_bounds__(P1_THREADS)
void pass1_kernel(const float2* __restrict__ pixel,      // [NLV*NB]
                  const float2* __restrict__ neigh,      // [NLV*NEI*NB]
                  const float2* __restrict__ params,     // [NLV*NPIX]
                  const void*   __restrict__ candA,
                  const void*   __restrict__ candB)
{
    const int swap = g_swap;
    const int mi32 = g_mask_i32;
    const void* maskp = swap ? candA : candB;
    const int*  nidx  = (const int*)(swap ? candB : candA);

    int t = blockIdx.x * P1_THREADS + threadIdx.x;   // t in [0, NLV*NB)
    int l = t >> NB_SHIFT;
    int b = t & (NB - 1);

    float2 p = pixel[t];
    float lat1 = p.x, lon1 = p.y;
    float cl1 = __cosf(lat1);

    int base = (l * NEI) * NB + b;
    const float2* ptab = params + l * NPIX;

    // Front-batch ALL coalesced streaming loads first (one MLP burst of up to
    // 24 outstanding loads per thread), then issue the dependent gathers.
    float2 q[NEI];
    int    m[NEI];
    int    id[NEI];
#pragma unroll
    for (int e = 0; e < NEI; e++)
        id[e] = nidx[base + e * NB];
#pragma unroll
    for (int e = 0; e < NEI; e++)
        q[e]  = neigh[base + e * NB];
    if (mi32) {
        const int* mp = (const int*)maskp;
#pragma unroll
        for (int e = 0; e < NEI; e++) m[e] = mp[base + e * NB];
    } else {
        const uint8_t* mp = (const uint8_t*)maskp;
#pragma unroll
        for (int e = 0; e < NEI; e++) m[e] = mp[base + e * NB];
    }

    // Predicated gathers: masked-off lanes generate no L1 wavefronts
    float2 pp[NEI];
#pragma unroll
    for (int e = 0; e < NEI; e++)
        pp[e] = m[e] ? ptab[id[e]] : make_float2(0.0f, 0.0f);

    float lmax = 0.0f;
    float s1x = 0.0f, s1y = 0.0f, s2x = 0.0f, s2y = 0.0f;
#pragma unroll
    for (int e = 0; e < NEI; e++) {
        float dlat = q[e].x - lat1;
        float dlon = q[e].y - lon1;
        float s1 = __sinf(0.5f * dlat);
        float s2 = __sinf(0.5f * dlon);
        float cl2 = __cosf(q[e].x);
        float a = fmaf(s1, s1, cl1 * cl2 * (s2 * s2));
        float d = dist_from_a(a);
        lmax = fmaxf(lmax, d);                 // max over ALL entries (ref semantics)
        s1x += pp[e].x;                        // pp already zeroed when masked
        s1y += pp[e].y;
        s2x = fmaf(d, pp[e].x, s2x);
        s2y = fmaf(d, pp[e].y, s2y);
    }

    g_sums[t] = make_float4(s1x, s1y, s2x, s2y);

    // warp + block max reduce
#pragma unroll
    for (int s = 16; s > 0; s >>= 1)
        lmax = fmaxf(lmax, __shfl_xor_sync(0xFFFFFFFFu, lmax, s));

    __shared__ float sm[P1_THREADS / 32];
    int lane = threadIdx.x & 31;
    int wid  = threadIdx.x >> 5;
    if (lane == 0) sm[wid] = lmax;
    __syncthreads();
    if (threadIdx.x == 0) {
        float bm = sm[0];
#pragma unroll
        for (int i = 1; i < P1_THREADS / 32; i++) bm = fmaxf(bm, sm[i]);
        g_blockmax[blockIdx.x] = bm;
    }
}

__global__ __launch_bounds__(1024)
void reduce_kernel()
{
    float m = 0.0f;
    for (int i = threadIdx.x; i < P1_BLOCKS; i += 1024)
        m = fmaxf(m, g_blockmax[i]);
#pragma unroll
    for (int s = 16; s > 0; s >>= 1)
        m = fmaxf(m, __shfl_xor_sync(0xFFFFFFFFu, m, s));
    __shared__ float sm[32];
    int lane = threadIdx.x & 31;
    int wid  = threadIdx.x >> 5;
    if (lane == 0) sm[wid] = m;
    __syncthreads();
    if (threadIdx.x == 0) {
        float bm = sm[0];
#pragma unroll
        for (int i = 1; i < 32; i++) bm = fmaxf(bm, sm[i]);
        g_max = bm;
    }
}

// ---------------------------------------------------------------------------
// Pass 2: trivial streaming combine  out[b][f*NLV+l] = gmax*S1 - S2
// ---------------------------------------------------------------------------
__global__ __launch_bounds__(P2_THREADS)
void pass2_kernel(float* __restrict__ out)               // [NB, 2*NLV]
{
    int b = blockIdx.x * P2_THREADS + threadIdx.x;
    float gmax = g_max;

    float o[2 * NLV];
#pragma unroll
    for (int l = 0; l < NLV; l++) {
        float4 s = g_sums[l * NB + b];       // coalesced across threads
        o[l]       = fmaf(gmax, s.x, -s.z);  // f = 0
        o[NLV + l] = fmaf(gmax, s.y, -s.w);  // f = 1
    }

    float4* o4 = reinterpret_cast<float4*>(out + (size_t)b * (2 * NLV));
#pragma unroll
    for (int i = 0; i < (2 * NLV) / 4; i++)
        o4[i] = make_float4(o[4 * i], o[4 * i + 1], o[4 * i + 2], o[4 * i + 3]);
}

extern "C" void kernel_launch(void* const* d_in, const int* in_sizes, int n_in,
                              void* d_out, int out_size)
{
    (void)out_size;
    // Size-based dispatch: robust to any input ordering.
    const float2* params = nullptr;
    const float2* pixel  = nullptr;
    const float2* neigh  = nullptr;
    const void*   candA  = nullptr;
    const void*   candB  = nullptr;
    for (int i = 0; i < n_in; i++) {
        switch (in_sizes[i]) {
            case SZ_PARAMS: params = (const float2*)d_in[i]; break;
            case SZ_PIXEL:  pixel  = (const float2*)d_in[i]; break;
            case SZ_NEIGH:  neigh  = (const float2*)d_in[i]; break;
            case SZ_IDXMSK:
                if (!candA) candA = d_in[i]; else candB = d_in[i];
                break;
            default: break;
        }
    }
    float* out = (float*)d_out;

    probe_kernel<<<1, 256>>>((const int*)candA, (const int*)candB);
    pass1_kernel<<<P1_BLOCKS, P1_THREADS>>>(pixel, neigh, params, candA, candB);
    reduce_kernel<<<1, 1024>>>();
    pass2_kernel<<<P2_BLOCKS, P2_THREADS>>>(out);
}